// round 15
// baseline (speedup 1.0000x reference)
#include <cuda_runtime.h>
#include <math.h>
#include <stdint.h>

#define BB 128
#define TT 512
#define HH 1024
#define NCTA 128
#define NTHR 544
#define NSTG 3

// smem: stage s<3 (49152B each): A 32KB @ s*49152 ([mb4][p32][row32] uint2),
//       B 16KB @ +32768. Zs float[128][72] @147456; sb @184320; mbars @184832
#define STAGE_SZ 49152
#define ZS_OFF   147456
#define SB_OFF   184320
#define MB_OFF   184832
#define EMPTY_MB(s)  (MB_OFF + (s) * 48)
#define B_MB(s)      (MB_OFF + (s) * 48 + 8)
#define A_MB(s, mb)  (MB_OFF + (s) * 48 + 16 + (mb) * 8)
#define SMEM_DYN 185088

// ---- persistent device state: packed (bf16-hi, bf16-lo) pairs ----
// A images: [t/parity][m-block][pair][row32], row stored at (m&31)^((p&3)<<2)
// B images: [ch][cb64][p][c64], col stored at c^((p&3)<<2)
__device__ __align__(16) uint2 g_x [TT][4][128][32];
__device__ __align__(16) uint2 g_h0[2][4][512][32];
__device__ __align__(16) uint2 g_h1[2][4][512][32];
__device__ __align__(16) uint2 g_w0[20][64][32][64];
__device__ __align__(16) uint2 g_w1[32][64][32][64];
__device__ int g_perm[BB];
__device__ int g_plen[BB];
__device__ int g_nt[TT];
__device__ unsigned g_cntI, g_genI, g_cntA, g_genA, g_cntB, g_genB;

__device__ __forceinline__ float sigf(float x) {
    return __fdividef(1.0f, 1.0f + __expf(-x));
}
__device__ __forceinline__ float tanf_fast(float x) {
    float cx = fminf(fmaxf(x, -15.0f), 15.0f);
    float e = __expf(2.0f * cx);
    return (e - 1.0f) * __fdividef(1.0f, e + 1.0f);
}

__device__ __forceinline__ uint32_t s2u(const void* p) {
    uint32_t a;
    asm("{ .reg .u64 t; cvta.to.shared.u64 t, %1; cvt.u32.u64 %0, t; }" : "=r"(a) : "l"(p));
    return a;
}
__device__ __forceinline__ uint2 pack_pair(float e0, float e1) {
    uint32_t hi, lo;
    asm("cvt.rn.bf16x2.f32 %0, %1, %2;" : "=r"(hi) : "f"(e1), "f"(e0));
    float r0 = e0 - __uint_as_float(hi << 16);
    float r1 = e1 - __uint_as_float(hi & 0xFFFF0000u);
    asm("cvt.rn.bf16x2.f32 %0, %1, %2;" : "=r"(lo) : "f"(r1), "f"(r0));
    return make_uint2(hi, lo);
}
__device__ __forceinline__ void bmma(float* c, uint32_t a0, uint32_t a1, uint32_t a2,
                                     uint32_t a3, uint32_t b0, uint32_t b1) {
    asm("mma.sync.aligned.m16n8k16.row.col.f32.bf16.bf16.f32 "
        "{%0,%1,%2,%3},{%4,%5,%6,%7},{%8,%9},{%0,%1,%2,%3};"
        : "+f"(c[0]), "+f"(c[1]), "+f"(c[2]), "+f"(c[3])
        : "r"(a0), "r"(a1), "r"(a2), "r"(a3), "r"(b0), "r"(b1));
}
__device__ __forceinline__ void mbar_init(uint32_t b, uint32_t n) {
    asm volatile("mbarrier.init.shared.b64 [%0], %1;" :: "r"(b), "r"(n) : "memory");
}
__device__ __forceinline__ void mexpect(uint32_t b, uint32_t tx) {
    asm volatile("mbarrier.arrive.expect_tx.shared.b64 _, [%0], %1;" :: "r"(b), "r"(tx) : "memory");
}
__device__ __forceinline__ void marrive(uint32_t b) {
    asm volatile("mbarrier.arrive.shared.b64 _, [%0];" :: "r"(b) : "memory");
}
__device__ __forceinline__ void mwait(uint32_t b, uint32_t ph) {
    asm volatile(
        "{\n\t.reg .pred P;\n"
        "W_%=:\n\t"
        "mbarrier.try_wait.parity.acquire.cta.shared::cta.b64 P, [%0], %1, 0x989680;\n\t"
        "@P bra D_%=;\n\t"
        "bra W_%=;\n"
        "D_%=:\n\t}"
        :: "r"(b), "r"(ph) : "memory");
}
__device__ __forceinline__ void bulk(uint32_t dst, const void* src, uint32_t bytes, uint32_t mbar) {
    asm volatile("cp.async.bulk.shared::cluster.global.mbarrier::complete_tx::bytes [%0], [%1], %2, [%3];"
        :: "r"(dst), "l"(src), "r"(bytes), "r"(mbar) : "memory");
}
__device__ __forceinline__ void barc() {   // compute-warps barrier (512 thr)
    asm volatile("bar.sync 1, 512;" ::: "memory");
}
__device__ __forceinline__ void arrive_evt(unsigned* cnt, unsigned* gen, unsigned nthr) {
    __threadfence();
    if (atomicAdd(cnt, 1u) == nthr - 1) {
        *cnt = 0;
        __threadfence();
        atomicAdd(gen, 1u);
    }
}
__device__ __forceinline__ void wait_gen(volatile unsigned* gen, unsigned base, unsigned want) {
    while (*gen - base < want) { __nanosleep(64); }
    __threadfence();
}

// ---- prep: sort rows by length (desc), alive counts ----
__global__ void prep_perm(const int* __restrict__ il) {
    __shared__ int sl[BB];
    int i = threadIdx.x;
    sl[i] = il[i];
    __syncthreads();
    int L = sl[i], r = 0;
    for (int j = 0; j < BB; j++) {
        int Lj = sl[j];
        if (Lj > L || (Lj == L && j < i)) r++;
    }
    g_perm[r] = i;
    g_plen[r] = L;
    for (int k = 0; k < 4; k++) {
        int t = i * 4 + k;
        int c = 0;
        for (int j = 0; j < BB; j++) c += (sl[j] > t);
        g_nt[t] = c;
    }
}

// ---- prep: embeddings -> g_x (permuted rows, block layout, A-swizzled) ----
__global__ void prep_x(const int* __restrict__ ib, const float* __restrict__ emb) {
    const int N = TT * 128 * BB;
    for (int i = blockIdx.x * blockDim.x + threadIdx.x; i < N;
         i += gridDim.x * blockDim.x) {
        int m = i & 127;
        int p = (i >> 7) & 127;
        int t = i >> 14;
        const float* s = emb + (size_t)ib[g_perm[m] * TT + t] * 256 + 2 * p;
        g_x[t][m >> 5][p][(m & 31) ^ ((p & 3) << 2)] = pack_pair(s[0], s[1]);
    }
}

// ---- prep: W -> packed [chunk][cb64][p][c64'] (B-swizzled) ----
__global__ void prep_w(const float* __restrict__ W0, const float* __restrict__ W1) {
    const long n0 = 20L * 64 * 32 * 64, n1 = 32L * 64 * 32 * 64;
    for (long i = (long)blockIdx.x * blockDim.x + threadIdx.x; i < n0 + n1;
         i += (long)gridDim.x * blockDim.x) {
        long j = i;
        const float* W = W0;
        uint2* dst = &g_w0[0][0][0][0];
        if (j >= n0) { j -= n0; W = W1; dst = &g_w1[0][0][0][0]; }
        int c  = (int)(j & 63);
        int p  = (int)((j >> 6) & 31);
        int cb = (int)((j >> 11) & 63);
        int ch = (int)(j >> 17);
        int gcol = ((c >> 4) & 3) * HH + cb * 16 + (c & 15);
        int k0 = 2 * (ch * 32 + p);
        dst[(j & ~63L) | (long)(c ^ ((p & 3) << 2))] =
            pack_pair(W[(size_t)k0 * 4096 + gcol],
                      W[(size_t)(k0 + 1) * 4096 + gcol]);
    }
}

__global__ void __launch_bounds__(NTHR, 1)
lstm_main(const int* __restrict__ il,
          const float* __restrict__ b0g,
          const float* __restrict__ b1g,
          float* __restrict__ out) {
    extern __shared__ char smem[];
    float* Zs = (float*)(smem + ZS_OFF);          // [128][72]
    float* sb = (float*)(smem + SB_OFF);          // 64 bias cols for this CTA's layer
    const uint32_t sbase = s2u(smem);

    const int tid = threadIdx.x;
    const int wid = tid >> 5, lid = tid & 31;
    const int cta = blockIdx.x;
    const int gid = cta >> 6;         // 0: layer0 stream, 1: layer1 stream
    const int c64 = cta & 63;         // owns gate-cols {g*1024 + c64*16 + u}
    const int g = lid >> 2, q = lid & 3;
    const int mt = wid >> 2;          // m-tile (32 rows)
    const int kh = (wid >> 1) & 1;    // K-half
    const int nh = wid & 1;           // N-half (32 cols)
    const int xr = q << 2;            // fragment swizzle

    const unsigned baseI = *(volatile unsigned*)&g_genI;
    const unsigned baseA = *(volatile unsigned*)&g_genA;
    const unsigned baseB = *(volatile unsigned*)&g_genB;

    if (tid == 0) {
        for (int s = 0; s < NSTG; s++) {
            mbar_init(sbase + EMPTY_MB(s), 16);
            mbar_init(sbase + B_MB(s), 1);
            for (int mb = 0; mb < 4; mb++) mbar_init(sbase + A_MB(s, mb), 1);
        }
    }
    if (tid < 64) {
        int gc = ((tid >> 4) & 3) * HH + c64 * 16 + (tid & 15);
        sb[tid] = gid ? b1g[gc] : b0g[gc];
    }
    {
        uint2 z2 = make_uint2(0u, 0u);
        uint2* z0 = &g_h0[0][0][0][0];
        uint2* z1 = &g_h1[0][0][0][0];
        for (int i = cta * NTHR + tid; i < 4 * 512 * 32; i += NCTA * NTHR) { z0[i] = z2; z1[i] = z2; }
    }
    __syncthreads();

    if (tid == 0) arrive_evt(&g_cntI, &g_genI, NCTA);
    wait_gen(&g_genI, baseI, 1u);

    if (wid == 16) {
        // ============ free-running producer (lanes 0..4) ============
        if (lid < 8) {
            int pstg = 0, pph = 1;
            for (int t = 0; t < TT; t++) {
                const int pr = t & 1, pw = pr ^ 1;
                const int nt = __ldg(&g_nt[t]);
                if (nt == 0) continue;
                const int nmb = (nt + 31) >> 5;

                if (gid == 0) {
                    // layer0(t): needs h0(t-1) [genA>=t] ; WAR vs group1 reads of h0(t-2) [genB>=t-1]
                    if (t >= 1) wait_gen(&g_genA, baseA, (unsigned)t);
                    if (t >= 2) wait_gen(&g_genB, baseB, (unsigned)(t - 1));
                    for (int c = 0; c < 20; c++) {
                        mwait(sbase + EMPTY_MB(pstg), (unsigned)pph);
                        if (lid < nmb) {
                            const uint2* ap = (c < 4) ? &g_x[t][lid][c * 32][0]
                                                      : &g_h0[pr][lid][(c - 4) * 32][0];
                            mexpect(sbase + A_MB(pstg, lid), 8192u);
                            bulk(sbase + pstg * STAGE_SZ + lid * 8192, ap, 8192u,
                                 sbase + A_MB(pstg, lid));
                        }
                        if (lid == 4) {
                            mexpect(sbase + B_MB(pstg), 16384u);
                            bulk(sbase + pstg * STAGE_SZ + 32768, &g_w0[c][c64][0][0],
                                 16384u, sbase + B_MB(pstg));
                        }
                        if (++pstg == NSTG) { pstg = 0; pph ^= 1; }
                    }
                } else {
                    // layer1(t): h1 chunks need end(t-1) [genB>=t]
                    wait_gen(&g_genB, baseB, (unsigned)t);
                    for (int i = 0; i < 16; i++) {
                        mwait(sbase + EMPTY_MB(pstg), (unsigned)pph);
                        if (lid < nmb) {
                            mexpect(sbase + A_MB(pstg, lid), 8192u);
                            bulk(sbase + pstg * STAGE_SZ + lid * 8192,
                                 &g_h1[pr][lid][i * 32][0], 8192u,
                                 sbase + A_MB(pstg, lid));
                        }
                        if (lid == 4) {
                            mexpect(sbase + B_MB(pstg), 16384u);
                            bulk(sbase + pstg * STAGE_SZ + 32768, &g_w1[16 + i][c64][0][0],
                                 16384u, sbase + B_MB(pstg));
                        }
                        if (++pstg == NSTG) { pstg = 0; pph ^= 1; }
                    }
                    // h0 chunks need mid(t) [genA>=t+1]
                    wait_gen(&g_genA, baseA, (unsigned)(t + 1));
                    for (int c = 0; c < 16; c++) {
                        mwait(sbase + EMPTY_MB(pstg), (unsigned)pph);
                        if (lid < nmb) {
                            mexpect(sbase + A_MB(pstg, lid), 8192u);
                            bulk(sbase + pstg * STAGE_SZ + lid * 8192,
                                 &g_h0[pw][lid][c * 32][0], 8192u,
                                 sbase + A_MB(pstg, lid));
                        }
                        if (lid == 4) {
                            mexpect(sbase + B_MB(pstg), 16384u);
                            bulk(sbase + pstg * STAGE_SZ + 32768, &g_w1[c][c64][0][0],
                                 16384u, sbase + B_MB(pstg));
                        }
                        if (++pstg == NSTG) { pstg = 0; pph ^= 1; }
                    }
                }
            }
        }
    } else {
        // ================= compute + cell (warps 0..15) =================
        const int m  = tid >> 1;          // valid for tid < 256
        const int uh = (tid & 1) * 8;     // 8 hidden units per thread
        float cs[8] = {0.f, 0.f, 0.f, 0.f, 0.f, 0.f, 0.f, 0.f};
        const int om    = (tid < 256) ? g_perm[m] : 0;
        const int mylen = (tid < 256) ? g_plen[m] : 0;
        const int nc = gid ? 32 : 20;
        int cstg = 0, cph = 0;

        for (int t = 0; t < TT; t++) {
            const int pw = (t & 1) ^ 1;
            const int nt = __ldg(&g_nt[t]);
            if (nt == 0) {
                if (tid == 0) {
                    if (gid == 0) arrive_evt(&g_cntA, &g_genA, 64u);
                    else          arrive_evt(&g_cntB, &g_genB, 64u);
                }
                continue;
            }
            const int nmb = (nt + 31) >> 5;
            const bool live = (mt < nmb);

            float C[2][4][4];
#pragma unroll
            for (int a = 0; a < 2; a++)
#pragma unroll
                for (int b = 0; b < 4; b++)
#pragma unroll
                    for (int d = 0; d < 4; d++) C[a][b][d] = 0.f;

            for (int ch = 0; ch < nc; ch++) {
                mwait(sbase + B_MB(cstg), (unsigned)cph);
                if (live) {
                    mwait(sbase + A_MB(cstg, mt), (unsigned)cph);
                    const uint2* Ab = (const uint2*)(smem + cstg * STAGE_SZ) + mt * 1024;
                    const uint2* Bb = (const uint2*)(smem + cstg * STAGE_SZ + 32768);
                    uint2 Af[2][2][4];
                    uint2 Bf[2][4][2];
#pragma unroll
                    for (int sl = 0; sl < 2; sl++) {
                        const int s  = kh * 2 + sl;
                        const int pa = (s * 8 + q) * 32;
                        const int pb = (s * 8 + q + 4) * 32;
#pragma unroll
                        for (int rt = 0; rt < 2; rt++) {
                            const int v0 = (rt * 16 + g) ^ xr;
                            const int v1 = (rt * 16 + g + 8) ^ xr;
                            Af[sl][rt][0] = Ab[pa + v0];
                            Af[sl][rt][1] = Ab[pa + v1];
                            Af[sl][rt][2] = Ab[pb + v0];
                            Af[sl][rt][3] = Ab[pb + v1];
                        }
                        const int ba  = (s * 8 + q) * 64;
                        const int bb2 = (s * 8 + q + 4) * 64;
#pragma unroll
                        for (int nt2 = 0; nt2 < 4; nt2++) {
                            const int cc = (nh * 32 + nt2 * 8 + g) ^ xr;
                            Bf[sl][nt2][0] = Bb[ba + cc];
                            Bf[sl][nt2][1] = Bb[bb2 + cc];
                        }
                    }
#pragma unroll
                    for (int sl = 0; sl < 2; sl++)
#pragma unroll
                        for (int rt = 0; rt < 2; rt++)
#pragma unroll
                            for (int nt2 = 0; nt2 < 4; nt2++) {
                                bmma(C[rt][nt2], Af[sl][rt][0].x, Af[sl][rt][1].x,
                                     Af[sl][rt][2].x, Af[sl][rt][3].x,
                                     Bf[sl][nt2][0].x, Bf[sl][nt2][1].x);
                                bmma(C[rt][nt2], Af[sl][rt][0].y, Af[sl][rt][1].y,
                                     Af[sl][rt][2].y, Af[sl][rt][3].y,
                                     Bf[sl][nt2][0].x, Bf[sl][nt2][1].x);
                                bmma(C[rt][nt2], Af[sl][rt][0].x, Af[sl][rt][1].x,
                                     Af[sl][rt][2].x, Af[sl][rt][3].x,
                                     Bf[sl][nt2][0].y, Bf[sl][nt2][1].y);
                            }
                }
                __syncwarp();
                if (lid == 0) marrive(sbase + EMPTY_MB(cstg));
                if (++cstg == NSTG) { cstg = 0; cph ^= 1; }
            }

            // reduce K-halves: kh0 store, kh1 add
            const int R = mt * 32;
            if (live && kh == 0) {
#pragma unroll
                for (int rt = 0; rt < 2; rt++)
#pragma unroll
                    for (int nt2 = 0; nt2 < 4; nt2++) {
                        const int col = nh * 32 + nt2 * 8 + 2 * q;
                        *(float2*)&Zs[(R + rt * 16 + g) * 72 + col] =
                            make_float2(C[rt][nt2][0], C[rt][nt2][1]);
                        *(float2*)&Zs[(R + rt * 16 + g + 8) * 72 + col] =
                            make_float2(C[rt][nt2][2], C[rt][nt2][3]);
                    }
            }
            barc();
            if (live && kh == 1) {
#pragma unroll
                for (int rt = 0; rt < 2; rt++)
#pragma unroll
                    for (int nt2 = 0; nt2 < 4; nt2++) {
                        const int col = nh * 32 + nt2 * 8 + 2 * q;
                        float2 v0 = *(float2*)&Zs[(R + rt * 16 + g) * 72 + col];
                        float2 v1 = *(float2*)&Zs[(R + rt * 16 + g + 8) * 72 + col];
                        v0.x += C[rt][nt2][0]; v0.y += C[rt][nt2][1];
                        v1.x += C[rt][nt2][2]; v1.y += C[rt][nt2][3];
                        *(float2*)&Zs[(R + rt * 16 + g) * 72 + col] = v0;
                        *(float2*)&Zs[(R + rt * 16 + g + 8) * 72 + col] = v1;
                    }
            }
            barc();

            // cell: alive rows only (threads 0..255), 8 units each
            if (tid < 256 && m < nt) {
                float nhv[8];
#pragma unroll
                for (int jj = 0; jj < 8; jj += 4) {
                    float4 vi = *(float4*)&Zs[m * 72 + 0  + uh + jj];
                    float4 vj = *(float4*)&Zs[m * 72 + 16 + uh + jj];
                    float4 vf = *(float4*)&Zs[m * 72 + 32 + uh + jj];
                    float4 vo = *(float4*)&Zs[m * 72 + 48 + uh + jj];
                    float ziv[4] = {vi.x, vi.y, vi.z, vi.w};
                    float zjv[4] = {vj.x, vj.y, vj.z, vj.w};
                    float zfv[4] = {vf.x, vf.y, vf.z, vf.w};
                    float zov[4] = {vo.x, vo.y, vo.z, vo.w};
#pragma unroll
                    for (int j = 0; j < 4; j++) {
                        int u = jj + j;
                        float zi = ziv[j] + sb[0  + uh + u - jj + jj];   // sb[uh+u]
                        zi = ziv[j] + sb[uh + u];
                        float zj = zjv[j] + sb[16 + uh + u];
                        float zf = zfv[j] + sb[32 + uh + u];
                        float zo = zov[j] + sb[48 + uh + u];
                        float nc2 = cs[u] * sigf(zf + 1.0f) + sigf(zi) * tanf_fast(zj);
                        nhv[u] = tanf_fast(nc2) * sigf(zo);
                        cs[u] = nc2;
                    }
                }
                const int mb = m >> 5;
                const int pgb = c64 * 8 + (tid & 1) * 4;
#pragma unroll
                for (int k = 0; k < 4; k++) {
                    uint2 pp = pack_pair(nhv[2 * k], nhv[2 * k + 1]);
                    const int pg = pgb + k;
                    const int mr = (m & 31) ^ ((pg & 3) << 2);
                    if (gid == 0) g_h0[pw][mb][pg][mr] = pp;
                    else          g_h1[pw][mb][pg][mr] = pp;
                }
                if (gid == 1 && t == mylen - 1) {
                    *(float4*)&out[om * HH + c64 * 16 + uh] =
                        make_float4(nhv[0], nhv[1], nhv[2], nhv[3]);
                    *(float4*)&out[om * HH + c64 * 16 + uh + 4] =
                        make_float4(nhv[4], nhv[5], nhv[6], nhv[7]);
                }
            }
            barc();   // h writes done before tid0 arrives; protects Zs reuse

            if (tid == 0) {
                if (gid == 0) arrive_evt(&g_cntA, &g_genA, 64u);  // mid(t)
                else          arrive_evt(&g_cntB, &g_genB, 64u);  // end(t)
            }
        }
    }
}

extern "C" void kernel_launch(void* const* d_in, const int* in_sizes, int n_in,
                              void* d_out, int out_size) {
    const int*   input_batch   = (const int*)d_in[0];
    const int*   input_lengths = (const int*)d_in[1];
    const float* emb           = (const float*)d_in[2];
    const float* W0            = (const float*)d_in[3];
    const float* b0            = (const float*)d_in[4];
    const float* W1            = (const float*)d_in[5];
    const float* b1            = (const float*)d_in[6];
    float*       out           = (float*)d_out;

    cudaFuncSetAttribute(lstm_main, cudaFuncAttributeMaxDynamicSharedMemorySize, SMEM_DYN);
    prep_perm<<<1, 128>>>(input_lengths);
    prep_x<<<1024, 256>>>(input_batch, emb);
    prep_w<<<2048, 256>>>(W0, W1);
    lstm_main<<<NCTA, NTHR, SMEM_DYN>>>(input_lengths, b0, b1, out);
}

// round 16
// speedup vs baseline: 1.2484x; 1.2484x over previous
#include <cuda_runtime.h>
#include <math.h>
#include <stdint.h>

#define BB 128
#define TT 512
#define HH 1024
#define NCTA 128
#define NTHR 544
#define NSTG 2

// smem: stage s<2 (81920B): A 64KB @ s*81920 ([mb4][pair64][row32] uint2), B 16KB @ +65536
//       ZsA @163840, ZsB @182272 (each float[128][36]); sb @200704; mbars @201216
#define STAGE_SZ 81920
#define ZSA_OFF  163840
#define ZSB_OFF  182272
#define SB_OFF   200704
#define MB_OFF   201216
#define EMPTY_MB(s)  (MB_OFF + (s) * 48)
#define B_MB(s)      (MB_OFF + (s) * 48 + 8)
#define A_MB(s, mb)  (MB_OFF + (s) * 48 + 16 + (mb) * 8)
#define SMEM_DYN 201472

// ---- persistent device state: packed (bf16-hi, bf16-lo) pairs ----
// A images: [t/parity][m-block][pair][row32], row stored at (m&31)^((p&3)<<2)
// B images: [bigchunk][cb][pair64][col32], col stored at c^((p&3)<<2)
__device__ __align__(16) uint2 g_x [TT][4][128][32];
__device__ __align__(16) uint2 g_h0[2][4][512][32];
__device__ __align__(16) uint2 g_h1[2][4][512][32];
__device__ __align__(16) uint2 g_w0[10][128][64][32];
__device__ __align__(16) uint2 g_w1[16][128][64][32];
__device__ int g_perm[BB];
__device__ int g_plen[BB];
__device__ int g_nt[TT];
__device__ unsigned g_cntA, g_genA, g_cntB, g_genB;

__device__ __forceinline__ float sigf(float x) {
    return __fdividef(1.0f, 1.0f + __expf(-x));
}
__device__ __forceinline__ float tanf_fast(float x) {
    float cx = fminf(fmaxf(x, -15.0f), 15.0f);
    float e = __expf(2.0f * cx);
    return (e - 1.0f) * __fdividef(1.0f, e + 1.0f);
}

__device__ __forceinline__ uint32_t s2u(const void* p) {
    uint32_t a;
    asm("{ .reg .u64 t; cvta.to.shared.u64 t, %1; cvt.u32.u64 %0, t; }" : "=r"(a) : "l"(p));
    return a;
}
__device__ __forceinline__ uint2 pack_pair(float e0, float e1) {
    uint32_t hi, lo;
    asm("cvt.rn.bf16x2.f32 %0, %1, %2;" : "=r"(hi) : "f"(e1), "f"(e0));
    float r0 = e0 - __uint_as_float(hi << 16);
    float r1 = e1 - __uint_as_float(hi & 0xFFFF0000u);
    asm("cvt.rn.bf16x2.f32 %0, %1, %2;" : "=r"(lo) : "f"(r1), "f"(r0));
    return make_uint2(hi, lo);
}
__device__ __forceinline__ void bmma(float* c, uint32_t a0, uint32_t a1, uint32_t a2,
                                     uint32_t a3, uint32_t b0, uint32_t b1) {
    asm("mma.sync.aligned.m16n8k16.row.col.f32.bf16.bf16.f32 "
        "{%0,%1,%2,%3},{%4,%5,%6,%7},{%8,%9},{%0,%1,%2,%3};"
        : "+f"(c[0]), "+f"(c[1]), "+f"(c[2]), "+f"(c[3])
        : "r"(a0), "r"(a1), "r"(a2), "r"(a3), "r"(b0), "r"(b1));
}
__device__ __forceinline__ void mbar_init(uint32_t b, uint32_t n) {
    asm volatile("mbarrier.init.shared.b64 [%0], %1;" :: "r"(b), "r"(n) : "memory");
}
__device__ __forceinline__ void mexpect(uint32_t b, uint32_t tx) {
    asm volatile("mbarrier.arrive.expect_tx.shared.b64 _, [%0], %1;" :: "r"(b), "r"(tx) : "memory");
}
__device__ __forceinline__ void marrive(uint32_t b) {
    asm volatile("mbarrier.arrive.shared.b64 _, [%0];" :: "r"(b) : "memory");
}
__device__ __forceinline__ void mwait(uint32_t b, uint32_t ph) {
    asm volatile(
        "{\n\t.reg .pred P;\n"
        "W_%=:\n\t"
        "mbarrier.try_wait.parity.acquire.cta.shared::cta.b64 P, [%0], %1, 0x989680;\n\t"
        "@P bra D_%=;\n\t"
        "bra W_%=;\n"
        "D_%=:\n\t}"
        :: "r"(b), "r"(ph) : "memory");
}
__device__ __forceinline__ void bulk(uint32_t dst, const void* src, uint32_t bytes, uint32_t mbar) {
    asm volatile("cp.async.bulk.shared::cluster.global.mbarrier::complete_tx::bytes [%0], [%1], %2, [%3];"
        :: "r"(dst), "l"(src), "r"(bytes), "r"(mbar) : "memory");
}
__device__ __forceinline__ void barc() {   // compute-warps barrier (512 thr)
    asm volatile("bar.sync 1, 512;" ::: "memory");
}
__device__ __forceinline__ void arrive_evt(unsigned* cnt, unsigned* gen) {
    __threadfence();
    if (atomicAdd(cnt, 1u) == NCTA - 1) {
        *cnt = 0;
        __threadfence();
        atomicAdd(gen, 1u);
    }
}
__device__ __forceinline__ void wait_gen(volatile unsigned* gen, unsigned base, unsigned want) {
    while (*gen - base < want) { __nanosleep(64); }
    __threadfence();
}

// ---- prep: sort rows by length (desc), alive counts ----
__global__ void prep_perm(const int* __restrict__ il) {
    __shared__ int sl[BB];
    int i = threadIdx.x;
    sl[i] = il[i];
    __syncthreads();
    int L = sl[i], r = 0;
    for (int j = 0; j < BB; j++) {
        int Lj = sl[j];
        if (Lj > L || (Lj == L && j < i)) r++;
    }
    g_perm[r] = i;
    g_plen[r] = L;
    for (int k = 0; k < 4; k++) {
        int t = i * 4 + k;
        int c = 0;
        for (int j = 0; j < BB; j++) c += (sl[j] > t);
        g_nt[t] = c;
    }
}

// ---- prep: embeddings -> g_x (permuted rows, block layout, A-swizzled) ----
__global__ void prep_x(const int* __restrict__ ib, const float* __restrict__ emb) {
    const int N = TT * 128 * BB;
    for (int i = blockIdx.x * blockDim.x + threadIdx.x; i < N;
         i += gridDim.x * blockDim.x) {
        int m = i & 127;
        int p = (i >> 7) & 127;
        int t = i >> 14;
        const float* s = emb + (size_t)ib[g_perm[m] * TT + t] * 256 + 2 * p;
        g_x[t][m >> 5][p][(m & 31) ^ ((p & 3) << 2)] = pack_pair(s[0], s[1]);
    }
}

// ---- prep: W -> packed [bigchunk][cb][pair64][col32'] (B-swizzled) ----
__global__ void prep_w(const float* __restrict__ W0, const float* __restrict__ W1) {
    const long n0 = 10L << 18, n1 = 16L << 18;   // 128*64*32 = 2^18 per chunk
    for (long i = (long)blockIdx.x * blockDim.x + threadIdx.x; i < n0 + n1;
         i += (long)gridDim.x * blockDim.x) {
        long j = i;
        const float* W = W0;
        uint2* dst = &g_w0[0][0][0][0];
        if (j >= n0) { j -= n0; W = W1; dst = &g_w1[0][0][0][0]; }
        int c  = (int)(j & 31);
        int p  = (int)((j >> 5) & 63);
        int cb = (int)((j >> 11) & 127);
        int ch = (int)(j >> 18);
        int gcol = ((c >> 3) & 3) * HH + cb * 8 + (c & 7);
        int k0 = 2 * (ch * 64 + p);
        dst[(j & ~31L) | (long)(c ^ ((p & 3) << 2))] =
            pack_pair(W[(size_t)k0 * 4096 + gcol],
                      W[(size_t)(k0 + 1) * 4096 + gcol]);
    }
}

__global__ void __launch_bounds__(NTHR, 1)
lstm_main(const int* __restrict__ il,
          const float* __restrict__ b0g,
          const float* __restrict__ b1g,
          float* __restrict__ out) {
    extern __shared__ char smem[];
    float* ZsA = (float*)(smem + ZSA_OFF);
    float* ZsB = (float*)(smem + ZSB_OFF);
    float* sb0 = (float*)(smem + SB_OFF);
    float* sb1 = (float*)(smem + SB_OFF + 128);
    const uint32_t sbase = s2u(smem);

    const int tid = threadIdx.x;
    const int wid = tid >> 5, lid = tid & 31;
    const int cta = blockIdx.x;
    const int g = lid >> 2, q = lid & 3;
    const int mt = wid >> 2;          // m-tile (32 rows), compute warps
    const int kq = wid & 3;           // K-quarter (16 pairs) of the chunk
    const int xr = q << 2;            // fragment swizzle

    const unsigned baseA = *(volatile unsigned*)&g_genA;
    const unsigned baseB = *(volatile unsigned*)&g_genB;

    if (tid == 0) {
        for (int s = 0; s < NSTG; s++) {
            mbar_init(sbase + EMPTY_MB(s), 16);
            mbar_init(sbase + B_MB(s), 1);
            for (int mb = 0; mb < 4; mb++) mbar_init(sbase + A_MB(s, mb), 1);
        }
    }
    if (tid < 32) {
        int gc = (tid >> 3) * HH + cta * 8 + (tid & 7);
        sb0[tid] = b0g[gc];
        sb1[tid] = b1g[gc];
    }
    {
        uint2 z2 = make_uint2(0u, 0u);
        uint2* z0 = &g_h0[0][0][0][0];
        uint2* z1 = &g_h1[0][0][0][0];
        for (int i = cta * NTHR + tid; i < 4 * 512 * 32; i += NCTA * NTHR) { z0[i] = z2; z1[i] = z2; }
    }
    __syncthreads();

    if (tid == 0) arrive_evt(&g_cntB, &g_genB);
    wait_gen(&g_genB, baseB, 1u);

    if (wid == 16) {
        // ============ dedicated free-running producer (lanes 0..4) ============
        if (lid < 8) {
            int pstg = 0, pph = 1;
            for (int t = 0; t < TT; t++) {
                const int pr = t & 1, pw = pr ^ 1;
                const int nt  = __ldg(&g_nt[t]);
                if (nt == 0) continue;
                const int nmb = (nt + 31) >> 5;

                // ---- layer 0: 10 big chunks (x: 0,1 ; h0[pr]: 2..9) ----
                for (int c = 0; c < 10; c++) {
                    mwait(sbase + EMPTY_MB(pstg), (unsigned)pph);
                    if (lid < nmb) {
                        const uint2* ap = (c < 2) ? &g_x[t][lid][c * 64][0]
                                                  : &g_h0[pr][lid][(c - 2) * 64][0];
                        mexpect(sbase + A_MB(pstg, lid), 16384u);
                        bulk(sbase + pstg * STAGE_SZ + lid * 16384, ap, 16384u,
                             sbase + A_MB(pstg, lid));
                    }
                    if (lid == 4) {
                        mexpect(sbase + B_MB(pstg), 16384u);
                        bulk(sbase + pstg * STAGE_SZ + 65536, &g_w0[c][cta][0][0],
                             16384u, sbase + B_MB(pstg));
                    }
                    if (++pstg == NSTG) { pstg = 0; pph ^= 1; }
                }
                // ---- layer 1 part A: h1[pr], 8 chunks (gate: end(t-1)) ----
                wait_gen(&g_genB, baseB, (unsigned)(t + 1));
                for (int i = 0; i < 8; i++) {
                    mwait(sbase + EMPTY_MB(pstg), (unsigned)pph);
                    if (lid < nmb) {
                        mexpect(sbase + A_MB(pstg, lid), 16384u);
                        bulk(sbase + pstg * STAGE_SZ + lid * 16384,
                             &g_h1[pr][lid][i * 64][0], 16384u,
                             sbase + A_MB(pstg, lid));
                    }
                    if (lid == 4) {
                        mexpect(sbase + B_MB(pstg), 16384u);
                        bulk(sbase + pstg * STAGE_SZ + 65536, &g_w1[8 + i][cta][0][0],
                             16384u, sbase + B_MB(pstg));
                    }
                    if (++pstg == NSTG) { pstg = 0; pph ^= 1; }
                }
                // ---- layer 1 part B: h0[pw], 8 chunks (gate: mid(t)) ----
                wait_gen(&g_genA, baseA, (unsigned)(t + 1));
                for (int c = 0; c < 8; c++) {
                    mwait(sbase + EMPTY_MB(pstg), (unsigned)pph);
                    if (lid < nmb) {
                        mexpect(sbase + A_MB(pstg, lid), 16384u);
                        bulk(sbase + pstg * STAGE_SZ + lid * 16384,
                             &g_h0[pw][lid][c * 64][0], 16384u,
                             sbase + A_MB(pstg, lid));
                    }
                    if (lid == 4) {
                        mexpect(sbase + B_MB(pstg), 16384u);
                        bulk(sbase + pstg * STAGE_SZ + 65536, &g_w1[c][cta][0][0],
                             16384u, sbase + B_MB(pstg));
                    }
                    if (++pstg == NSTG) { pstg = 0; pph ^= 1; }
                }
            }
        }
    } else {
        // ================= compute + cell (warps 0..15) =================
        const int m  = tid >> 1;          // valid for tid < 256
        const int uh = (tid & 1) * 4;
        float cs0[4] = {0.f, 0.f, 0.f, 0.f};
        float cs1[4] = {0.f, 0.f, 0.f, 0.f};
        const int om    = (tid < 256) ? g_perm[m] : 0;
        const int mylen = (tid < 256) ? g_plen[m] : 0;
        int cstg = 0, cph = 0;

        for (int t = 0; t < TT; t++) {
            const int pw = (t & 1) ^ 1;
            const int nt = __ldg(&g_nt[t]);
            for (int layer = 0; layer < 2; layer++) {
                if (nt == 0) {
                    if (tid == 0) {
                        if (layer == 0) arrive_evt(&g_cntA, &g_genA);
                        else            arrive_evt(&g_cntB, &g_genB);
                    }
                    continue;
                }
                const int nc = layer ? 16 : 10;
                const int nmb = (nt + 31) >> 5;
                const bool live = (mt < nmb);

                float C[2][4][4];
#pragma unroll
                for (int a = 0; a < 2; a++)
#pragma unroll
                    for (int b = 0; b < 4; b++)
#pragma unroll
                        for (int d = 0; d < 4; d++) C[a][b][d] = 0.f;

                for (int ch = 0; ch < nc; ch++) {
                    mwait(sbase + B_MB(cstg), (unsigned)cph);
                    if (live) {
                        mwait(sbase + A_MB(cstg, mt), (unsigned)cph);
                        const uint2* Ab = (const uint2*)(smem + cstg * STAGE_SZ) + mt * 2048;
                        const uint2* Bb = (const uint2*)(smem + cstg * STAGE_SZ + 65536);
#pragma unroll
                        for (int sl = 0; sl < 2; sl++) {
                            const int pa = (kq * 16 + sl * 8 + q) * 32;
                            const int pb = (kq * 16 + sl * 8 + q + 4) * 32;
                            uint2 Af[2][4];
                            uint2 Bf[4][2];
#pragma unroll
                            for (int rt = 0; rt < 2; rt++) {
                                const int v0 = (rt * 16 + g) ^ xr;
                                const int v1 = (rt * 16 + g + 8) ^ xr;
                                Af[rt][0] = Ab[pa + v0];
                                Af[rt][1] = Ab[pa + v1];
                                Af[rt][2] = Ab[pb + v0];
                                Af[rt][3] = Ab[pb + v1];
                            }
#pragma unroll
                            for (int nt2 = 0; nt2 < 4; nt2++) {
                                const int cc = (nt2 * 8 + g) ^ xr;
                                Bf[nt2][0] = Bb[pa + cc];
                                Bf[nt2][1] = Bb[pb + cc];
                            }
#pragma unroll
                            for (int rt = 0; rt < 2; rt++)
#pragma unroll
                                for (int nt2 = 0; nt2 < 4; nt2++) {
                                    bmma(C[rt][nt2], Af[rt][0].x, Af[rt][1].x,
                                         Af[rt][2].x, Af[rt][3].x,
                                         Bf[nt2][0].x, Bf[nt2][1].x);
                                    bmma(C[rt][nt2], Af[rt][0].y, Af[rt][1].y,
                                         Af[rt][2].y, Af[rt][3].y,
                                         Bf[nt2][0].x, Bf[nt2][1].x);
                                    bmma(C[rt][nt2], Af[rt][0].x, Af[rt][1].x,
                                         Af[rt][2].x, Af[rt][3].x,
                                         Bf[nt2][0].y, Bf[nt2][1].y);
                                }
                        }
                    }
                    __syncwarp();
                    if (lid == 0) marrive(sbase + EMPTY_MB(cstg));
                    if (++cstg == NSTG) { cstg = 0; cph ^= 1; }
                }

                // staged 4-way reduction: kq0->ZsA, kq2->ZsB; then kq1 +=A, kq3 +=B
                const int R = mt * 32;
                float* Zdst = (kq & 2) ? ZsB : ZsA;
                if (live && (kq == 0 || kq == 2)) {
#pragma unroll
                    for (int rt = 0; rt < 2; rt++)
#pragma unroll
                        for (int nt2 = 0; nt2 < 4; nt2++) {
                            const int col = nt2 * 8 + 2 * q;
                            *(float2*)&Zdst[(R + rt * 16 + g) * 36 + col] =
                                make_float2(C[rt][nt2][0], C[rt][nt2][1]);
                            *(float2*)&Zdst[(R + rt * 16 + g + 8) * 36 + col] =
                                make_float2(C[rt][nt2][2], C[rt][nt2][3]);
                        }
                }
                barc();
                if (live && (kq == 1 || kq == 3)) {
#pragma unroll
                    for (int rt = 0; rt < 2; rt++)
#pragma unroll
                        for (int nt2 = 0; nt2 < 4; nt2++) {
                            const int col = nt2 * 8 + 2 * q;
                            float2 v0 = *(float2*)&Zdst[(R + rt * 16 + g) * 36 + col];
                            float2 v1 = *(float2*)&Zdst[(R + rt * 16 + g + 8) * 36 + col];
                            v0.x += C[rt][nt2][0]; v0.y += C[rt][nt2][1];
                            v1.x += C[rt][nt2][2]; v1.y += C[rt][nt2][3];
                            *(float2*)&Zdst[(R + rt * 16 + g) * 36 + col] = v0;
                            *(float2*)&Zdst[(R + rt * 16 + g + 8) * 36 + col] = v1;
                        }
                }
                barc();

                // cell: alive rows only (threads 0..255)
                if (tid < 256 && m < nt) {
                    const float* sb = layer ? sb1 : sb0;
                    float* cs = layer ? cs1 : cs0;
                    float4 ai = *(float4*)&ZsA[m * 36 + 0 + uh];
                    float4 aj = *(float4*)&ZsA[m * 36 + 8 + uh];
                    float4 af = *(float4*)&ZsA[m * 36 + 16 + uh];
                    float4 ao = *(float4*)&ZsA[m * 36 + 24 + uh];
                    float4 bi = *(float4*)&ZsB[m * 36 + 0 + uh];
                    float4 bj = *(float4*)&ZsB[m * 36 + 8 + uh];
                    float4 bf = *(float4*)&ZsB[m * 36 + 16 + uh];
                    float4 bo = *(float4*)&ZsB[m * 36 + 24 + uh];
                    float ziv[4] = {ai.x + bi.x, ai.y + bi.y, ai.z + bi.z, ai.w + bi.w};
                    float zjv[4] = {aj.x + bj.x, aj.y + bj.y, aj.z + bj.z, aj.w + bj.w};
                    float zfv[4] = {af.x + bf.x, af.y + bf.y, af.z + bf.z, af.w + bf.w};
                    float zov[4] = {ao.x + bo.x, ao.y + bo.y, ao.z + bo.z, ao.w + bo.w};
                    float nh[4];
#pragma unroll
                    for (int j = 0; j < 4; j++) {
                        float zi = ziv[j] + sb[uh + j];
                        float zj = zjv[j] + sb[8 + uh + j];
                        float zf = zfv[j] + sb[16 + uh + j];
                        float zo = zov[j] + sb[24 + uh + j];
                        float nc2 = cs[j] * sigf(zf + 1.0f) + sigf(zi) * tanf_fast(zj);
                        nh[j] = tanf_fast(nc2) * sigf(zo);
                        cs[j] = nc2;
                    }
                    uint2 p0 = pack_pair(nh[0], nh[1]);
                    uint2 p1 = pack_pair(nh[2], nh[3]);
                    const int pg = cta * 4 + (tid & 1) * 2;
                    const int mb = m >> 5;
                    const int m0 = (m & 31) ^ ((pg & 3) << 2);
                    const int m1 = (m & 31) ^ (((pg + 1) & 3) << 2);
                    if (layer == 0) {
                        g_h0[pw][mb][pg][m0] = p0;
                        g_h0[pw][mb][pg + 1][m1] = p1;
                    } else {
                        g_h1[pw][mb][pg][m0] = p0;
                        g_h1[pw][mb][pg + 1][m1] = p1;
                        if (t == mylen - 1)
                            *(float4*)&out[om * HH + cta * 8 + uh] =
                                make_float4(nh[0], nh[1], nh[2], nh[3]);
                    }
                }
                barc();   // h writes done before tid0 arrives; protects Zs reuse

                if (tid == 0) {
                    if (layer == 0) arrive_evt(&g_cntA, &g_genA);  // mid(t)
                    else            arrive_evt(&g_cntB, &g_genB);  // end(t)
                }
            }
        }
    }
}

extern "C" void kernel_launch(void* const* d_in, const int* in_sizes, int n_in,
                              void* d_out, int out_size) {
    const int*   input_batch   = (const int*)d_in[0];
    const int*   input_lengths = (const int*)d_in[1];
    const float* emb           = (const float*)d_in[2];
    const float* W0            = (const float*)d_in[3];
    const float* b0            = (const float*)d_in[4];
    const float* W1            = (const float*)d_in[5];
    const float* b1            = (const float*)d_in[6];
    float*       out           = (float*)d_out;

    cudaFuncSetAttribute(lstm_main, cudaFuncAttributeMaxDynamicSharedMemorySize, SMEM_DYN);
    prep_perm<<<1, 128>>>(input_lengths);
    prep_x<<<1024, 256>>>(input_batch, emb);
    prep_w<<<2048, 256>>>(W0, W1);
    lstm_main<<<NCTA, NTHR, SMEM_DYN>>>(input_lengths, b0, b1, out);
}